// round 3
// baseline (speedup 1.0000x reference)
#include <cuda_runtime.h>

// PWC-Net correlation (MAX_DISP=4 -> 81 channels) + LeakyReLU(0.1), /C normalize.
// feat1, feat2: [N=8, C=256, H=80, W=160] fp32. out: [N, 81, H, W] fp32.
//
// One block per (n, y). 9 warps: warp w handles dy=w. Lane handles 5 consecutive
// x pixels (32*5 = 160 = W). 45 fp32 accumulators per thread (5 px x 9 dx).
// Channels processed in chunks of CC=4 staged through shared memory.
// R2: identical resubmit of R1 (R1 failed on container infra, not kernel).

#define MAXD 4
#define DD   9           // 2*MAXD+1
#define NCH  81          // DD*DD
#define C_   256
#define H_   80
#define W_   160
#define N_   8
#define CC   4           // channel chunk
#define P_   5           // pixels per thread
#define F2W  (W_ + 2*MAXD)   // 168 padded row
#define NTHREADS (DD * 32)   // 288

__global__ __launch_bounds__(NTHREADS, 2)
void corr_leaky_kernel(const float* __restrict__ f1,
                       const float* __restrict__ f2,
                       float* __restrict__ out)
{
    __shared__ float s1[CC][W_];        // f1 chunk: [cc][x]
    __shared__ float s2[CC][DD][F2W];   // f2 chunk: [cc][row dy][x+4 shifted, zero-padded]

    const int bid  = blockIdx.x;        // 0 .. N_*H_-1
    const int n    = bid / H_;
    const int y    = bid - n * H_;
    const int tid  = threadIdx.x;
    const int dy   = tid >> 5;          // warp id = dy (0..8)
    const int lane = tid & 31;
    const int x0   = lane * P_;         // first pixel this thread owns

    float acc[P_][DD];
#pragma unroll
    for (int p = 0; p < P_; p++)
#pragma unroll
        for (int dx = 0; dx < DD; dx++) acc[p][dx] = 0.0f;

    const int img_base = n * C_ * H_ * W_;   // fits in int (max ~26M)

    for (int c0 = 0; c0 < C_; c0 += CC) {
        __syncthreads();   // protect smem from previous iteration's readers

        // ---- stage f1 chunk: CC*W_ = 640 floats ----
        for (int t = tid; t < CC * W_; t += NTHREADS) {
            const int c = t / W_;
            const int x = t - c * W_;
            s1[c][x] = f1[img_base + (c0 + c) * (H_ * W_) + y * W_ + x];
        }

        // ---- stage f2 chunk: CC*DD*F2W = 6048 floats, zero-padded borders ----
        for (int t = tid; t < CC * DD * F2W; t += NTHREADS) {
            const int c   = t / (DD * F2W);
            const int rem = t - c * (DD * F2W);
            const int r   = rem / F2W;
            const int j   = rem - r * F2W;
            const int gy  = y + r - MAXD;
            const int gx  = j - MAXD;
            float v = 0.0f;
            if ((unsigned)gy < (unsigned)H_ && (unsigned)gx < (unsigned)W_)
                v = f2[img_base + (c0 + c) * (H_ * W_) + gy * W_ + gx];
            s2[c][r][j] = v;
        }

        __syncthreads();

        // ---- compute: per channel, 18 LDS feeds 45 FFMA (ratio 2.5 -> FMA-bound) ----
#pragma unroll
        for (int cc = 0; cc < CC; cc++) {
            float a[P_];
            float b[P_ + DD - 1];        // 13 window values
#pragma unroll
            for (int p = 0; p < P_; p++) a[p] = s1[cc][x0 + p];
#pragma unroll
            for (int k = 0; k < P_ + DD - 1; k++) b[k] = s2[cc][dy][x0 + k];
#pragma unroll
            for (int p = 0; p < P_; p++)
#pragma unroll
                for (int dx = 0; dx < DD; dx++)
                    acc[p][dx] = fmaf(a[p], b[p + dx], acc[p][dx]);
        }
    }

    // ---- epilogue: /C, LeakyReLU(0.1), store ----
    const float scale = 1.0f / (float)C_;
    const int out_base = n * NCH * H_ * W_ + y * W_;
#pragma unroll
    for (int dx = 0; dx < DD; dx++) {
        const int ch = dy * DD + dx;
        float* orow = out + out_base + ch * (H_ * W_);
#pragma unroll
        for (int p = 0; p < P_; p++) {
            float v = acc[p][dx] * scale;
            v = (v > 0.0f) ? v : 0.1f * v;
            orow[x0 + p] = v;
        }
    }
}

extern "C" void kernel_launch(void* const* d_in, const int* in_sizes, int n_in,
                              void* d_out, int out_size)
{
    const float* feat1 = (const float*)d_in[0];
    const float* feat2 = (const float*)d_in[1];
    float* out = (float*)d_out;
    corr_leaky_kernel<<<N_ * H_, NTHREADS>>>(feat1, feat2, out);
}

// round 6
// speedup vs baseline: 1.4964x; 1.4964x over previous
#include <cuda_runtime.h>

// PWC-Net correlation (MAX_DISP=4 -> 81 channels) + LeakyReLU(0.1), /C normalize.
// feat1, feat2: [N=8, C=256, H=80, W=160] fp32. out: [N, 81, H, W] fp32.
//
// One block per (n, y). 9 warps: warp w handles dy=w (both staging row w and
// compute row w). Lane owns 5 consecutive x pixels. 45 accumulators/thread.
// R4: staging rewritten — warp-owns-row, float4, zero divisions. R3 ncu showed
// alu=34% > fma=16.5%: scalar div-heavy staging was the bottleneck.
// R5: identical resubmit of R4 (R4 hit broker infra failure, never ran).

#define MAXD 4
#define DD   9           // 2*MAXD+1
#define NCH  81          // DD*DD
#define C_   256
#define H_   80
#define W_   160
#define N_   8
#define CC   4           // channel chunk
#define P_   5           // pixels per thread
#define F2W  (W_ + 2*MAXD)   // 168 floats per padded row = 42 float4 (672B, 16B-mult)
#define NQ4  (F2W / 4)       // 42 float4 slots
#define NTHREADS (DD * 32)   // 288

__global__ __launch_bounds__(NTHREADS, 2)
void corr_leaky_kernel(const float* __restrict__ f1,
                       const float* __restrict__ f2,
                       float* __restrict__ out)
{
    __shared__ __align__(16) float s1[CC][W_];        // f1 chunk: [c][x]
    __shared__ __align__(16) float s2[CC][DD][F2W];   // f2 chunk: [c][row][x+4], zero-padded

    const int bid  = blockIdx.x;        // 0 .. N_*H_-1
    const int n    = bid / H_;
    const int y    = bid - n * H_;
    const int tid  = threadIdx.x;
    const int dy   = tid >> 5;          // warp id = row it stages AND computes
    const int lane = tid & 31;
    const int x0   = lane * P_;

    float acc[P_][DD];
#pragma unroll
    for (int p = 0; p < P_; p++)
#pragma unroll
        for (int dx = 0; dx < DD; dx++) acc[p][dx] = 0.0f;

    const int img_base = n * C_ * H_ * W_;

    // f2 row this warp stages: gy = y + dy - MAXD (per-warp constant predicate)
    const int  gy    = y + dy - MAXD;
    const bool rowok = ((unsigned)gy < (unsigned)H_);

    // f1 staging assignment: one float4 per thread, tid < CC*40
    const int f1c  = tid / 40;              // constant division (mul-hi), once
    const int f1j4 = tid - f1c * 40;
    const bool f1ok = (tid < CC * (W_ / 4));

    for (int c0 = 0; c0 < C_; c0 += CC) {
        __syncthreads();   // protect smem from previous iteration's readers

        // ---- stage f1 chunk: 160 float4, one per thread ----
        if (f1ok) {
            const float* r1 = f1 + img_base + (c0 + f1c) * (H_ * W_) + y * W_;
            *(float4*)&s1[f1c][4 * f1j4] = *(const float4*)(r1 + 4 * f1j4);
        }

        // ---- stage f2 chunk: warp dy stages padded row dy for all CC channels.
        //      42 float4 slots/row: lane -> slot lane; lanes<10 -> slot 32+lane.
        //      Slot j4 interior load: gx0 = 4*j4-4 (16B aligned). Slots 0,41 = pad.
#pragma unroll
        for (int c = 0; c < CC; c++) {
            const float* rowp = f2 + img_base + (c0 + c) * (H_ * W_) + gy * W_;
            {
                const int j4 = lane;
                float4 v = make_float4(0.f, 0.f, 0.f, 0.f);
                if (rowok && j4 != 0)
                    v = *(const float4*)(rowp + 4 * j4 - 4);
                *(float4*)&s2[c][dy][4 * j4] = v;
            }
            if (lane < NQ4 - 32) {          // lanes 0..9 -> slots 32..41
                const int j4 = 32 + lane;
                float4 v = make_float4(0.f, 0.f, 0.f, 0.f);
                if (rowok && j4 != NQ4 - 1)
                    v = *(const float4*)(rowp + 4 * j4 - 4);
                *(float4*)&s2[c][dy][4 * j4] = v;
            }
        }

        __syncthreads();

        // ---- compute: per channel 18 LDS feed 45 FFMA ----
#pragma unroll
        for (int cc = 0; cc < CC; cc++) {
            float a[P_];
            float b[P_ + DD - 1];           // 13-wide window
#pragma unroll
            for (int p = 0; p < P_; p++) a[p] = s1[cc][x0 + p];
#pragma unroll
            for (int k = 0; k < P_ + DD - 1; k++) b[k] = s2[cc][dy][x0 + k];
#pragma unroll
            for (int p = 0; p < P_; p++)
#pragma unroll
                for (int dx = 0; dx < DD; dx++)
                    acc[p][dx] = fmaf(a[p], b[p + dx], acc[p][dx]);
        }
    }

    // ---- epilogue: /C, LeakyReLU(0.1), store ----
    const float scale = 1.0f / (float)C_;
    const int out_base = n * NCH * H_ * W_ + y * W_;
#pragma unroll
    for (int dx = 0; dx < DD; dx++) {
        const int ch = dy * DD + dx;
        float* orow = out + out_base + ch * (H_ * W_);
#pragma unroll
        for (int p = 0; p < P_; p++) {
            float v = acc[p][dx] * scale;
            v = (v > 0.0f) ? v : 0.1f * v;
            orow[x0 + p] = v;
        }
    }
}

extern "C" void kernel_launch(void* const* d_in, const int* in_sizes, int n_in,
                              void* d_out, int out_size)
{
    const float* feat1 = (const float*)d_in[0];
    const float* feat2 = (const float*)d_in[1];
    float* out = (float*)d_out;
    corr_leaky_kernel<<<N_ * H_, NTHREADS>>>(feat1, feat2, out);
}

// round 7
// speedup vs baseline: 4.7422x; 3.1692x over previous
#include <cuda_runtime.h>

// PWC-Net correlation (MAX_DISP=4 -> 81 channels) + LeakyReLU(0.1), /C normalize.
// feat1, feat2: [N=8, C=256, H=80, W=160] fp32. out: [N, 81, H, W] fp32.
//
// One block per (n, y). 9 warps: warp w owns row dy=w (stages it and computes it).
// Lane owns 5 consecutive x pixels. 45 fp32 accumulators/thread.
// R6: cp.async (LDGSTS) double-buffered pipeline. R5 ncu: issue=17%, all pipes
// idle -> per-chunk serial LDG->sync->compute exposed full memory latency 64x.
// Now chunk i+1 loads overlap chunk i compute; one __syncthreads per chunk.

#define MAXD 4
#define DD   9           // 2*MAXD+1
#define NCH  81          // DD*DD
#define C_   256
#define H_   80
#define W_   160
#define N_   8
#define HW_  (H_ * W_)
#define CC   4           // channel chunk
#define P_   5           // pixels per thread
#define F2W  (W_ + 2*MAXD)   // 168 floats per padded row = 42 float4 slots
#define NQ4  (F2W / 4)       // 42
#define NTHREADS (DD * 32)   // 288
#define NCHUNK (C_ / CC)     // 64

// dynamic smem layout: s1[2][CC][W_] | s2[2][CC][DD][F2W]
#define S1_FLOATS (2 * CC * W_)                 // 1280
#define S2_FLOATS (2 * CC * DD * F2W)           // 12096
#define SMEM_BYTES ((S1_FLOATS + S2_FLOATS) * 4)  // 53504 B

__device__ __forceinline__ void cp16(float* dst_smem, const float* src_gmem) {
    unsigned d = (unsigned)__cvta_generic_to_shared(dst_smem);
    asm volatile("cp.async.cg.shared.global [%0], [%1], 16;" :: "r"(d), "l"(src_gmem));
}
#define CP_COMMIT() asm volatile("cp.async.commit_group;")
#define CP_WAIT0()  asm volatile("cp.async.wait_group 0;" ::: "memory")

__global__ __launch_bounds__(NTHREADS, 2)
void corr_leaky_kernel(const float* __restrict__ f1,
                       const float* __restrict__ f2,
                       float* __restrict__ out)
{
    extern __shared__ __align__(16) float smem[];
    float* s1 = smem;               // [2][CC][W_]
    float* s2 = smem + S1_FLOATS;   // [2][CC][DD][F2W]
#define S1REF(b,c,x)   s1[((b)*CC + (c))*W_ + (x)]
#define S2REF(b,c,r,j) s2[(((b)*CC + (c))*DD + (r))*F2W + (j)]

    const int bid  = blockIdx.x;        // 0 .. N_*H_-1
    const int n    = bid / H_;
    const int y    = bid - n * H_;
    const int tid  = threadIdx.x;
    const int dy   = tid >> 5;
    const int lane = tid & 31;
    const int x0   = lane * P_;

    const int img_base = n * C_ * HW_;
    const int  gy    = y + dy - MAXD;
    const bool rowok = ((unsigned)gy < (unsigned)H_);

    // f1 staging: one float4 per thread for tid < 160
    const int f1c  = tid / 40;
    const int f1j4 = tid - f1c * 40;
    const bool f1ok = (tid < CC * (W_ / 4));
    const float* f1base = f1 + img_base + y * W_;     // + c*HW_ + 4*f1j4 per chunk
    const float* f2base = f2 + img_base + gy * W_;    // + c*HW_ per chunk

    // ---- pre-zero fixed pad slots in BOTH buffers (written once, never overwritten) ----
    const float4 z4 = make_float4(0.f, 0.f, 0.f, 0.f);
#pragma unroll
    for (int b = 0; b < 2; b++)
#pragma unroll
        for (int c = 0; c < CC; c++) {
            if (rowok) {
                if (lane == 0) *(float4*)&S2REF(b, c, dy, 0) = z4;
                if (lane == 1) *(float4*)&S2REF(b, c, dy, 4 * (NQ4 - 1)) = z4;
            } else {
                *(float4*)&S2REF(b, c, dy, 4 * lane) = z4;
                if (lane < NQ4 - 32) *(float4*)&S2REF(b, c, dy, 4 * (32 + lane)) = z4;
            }
        }

    float acc[P_][DD];
#pragma unroll
    for (int p = 0; p < P_; p++)
#pragma unroll
        for (int dx = 0; dx < DD; dx++) acc[p][dx] = 0.0f;

    // ---- prologue: prefetch chunk 0 into buffer 0 ----
    {
        if (f1ok) cp16(&S1REF(0, f1c, 4 * f1j4), f1base + f1c * HW_ + 4 * f1j4);
        if (rowok) {
#pragma unroll
            for (int c = 0; c < CC; c++) {
                const float* rowp = f2base + c * HW_;
                if (lane >= 1)  cp16(&S2REF(0, c, dy, 4 * lane),        rowp + 4 * lane - 4);
                if (lane <= 8)  cp16(&S2REF(0, c, dy, 4 * (32 + lane)), rowp + 4 * (32 + lane) - 4);
            }
        }
        CP_COMMIT();
    }

    for (int i = 0; i < NCHUNK; i++) {
        const int cur = i & 1;
        CP_WAIT0();
        __syncthreads();   // buf[cur] data visible to all; prior readers of buf[cur^1] done

        // ---- prefetch chunk i+1 into the other buffer (overlaps compute below) ----
        if (i + 1 < NCHUNK) {
            const int nb = cur ^ 1;
            const int c0 = (i + 1) * CC;
            if (f1ok) cp16(&S1REF(nb, f1c, 4 * f1j4),
                           f1base + (c0 + f1c) * HW_ + 4 * f1j4);
            if (rowok) {
#pragma unroll
                for (int c = 0; c < CC; c++) {
                    const float* rowp = f2base + (c0 + c) * HW_;
                    if (lane >= 1)  cp16(&S2REF(nb, c, dy, 4 * lane),        rowp + 4 * lane - 4);
                    if (lane <= 8)  cp16(&S2REF(nb, c, dy, 4 * (32 + lane)), rowp + 4 * (32 + lane) - 4);
                }
            }
            CP_COMMIT();
        }

        // ---- compute on buf[cur]: per channel 18 LDS feed 45 FFMA ----
#pragma unroll
        for (int cc = 0; cc < CC; cc++) {
            float a[P_];
            float b[P_ + DD - 1];
#pragma unroll
            for (int p = 0; p < P_; p++) a[p] = S1REF(cur, cc, x0 + p);
#pragma unroll
            for (int k = 0; k < P_ + DD - 1; k++) b[k] = S2REF(cur, cc, dy, x0 + k);
#pragma unroll
            for (int p = 0; p < P_; p++)
#pragma unroll
                for (int dx = 0; dx < DD; dx++)
                    acc[p][dx] = fmaf(a[p], b[p + dx], acc[p][dx]);
        }
    }

    // ---- epilogue: /C, LeakyReLU(0.1), store ----
    const float scale = 1.0f / (float)C_;
    const int out_base = n * NCH * HW_ + y * W_;
#pragma unroll
    for (int dx = 0; dx < DD; dx++) {
        const int ch = dy * DD + dx;
        float* orow = out + out_base + ch * HW_;
#pragma unroll
        for (int p = 0; p < P_; p++) {
            float v = acc[p][dx] * scale;
            v = (v > 0.0f) ? v : 0.1f * v;
            orow[x0 + p] = v;
        }
    }
}

extern "C" void kernel_launch(void* const* d_in, const int* in_sizes, int n_in,
                              void* d_out, int out_size)
{
    const float* feat1 = (const float*)d_in[0];
    const float* feat2 = (const float*)d_in[1];
    float* out = (float*)d_out;
    cudaFuncSetAttribute(corr_leaky_kernel,
                         cudaFuncAttributeMaxDynamicSharedMemorySize, SMEM_BYTES);
    corr_leaky_kernel<<<N_ * H_, NTHREADS, SMEM_BYTES>>>(feat1, feat2, out);
}

// round 8
// speedup vs baseline: 5.1130x; 1.0782x over previous
#include <cuda_runtime.h>

// PWC-Net correlation (MAX_DISP=4 -> 81 channels) + LeakyReLU(0.1), /C normalize.
// feat1, feat2: [N=8, C=256, H=80, W=160] fp32. out: [N, 81, H, W] fp32.
//
// R6: cp.async double-buffered pipeline -> 250 us.
// R7: persistent grid (296 blocks = 2/SM) + atomic row distribution.
//     R6 ncu arithmetic: 640 CTAs over 296 slots -> 48 SMs ran 3 CTA-rounds
//     (makespan 1.39x mean) while busy SMs were ~90-100% issue-bound.
//     Dynamic row grab removes the wave-quantization tail.

#define MAXD 4
#define DD   9
#define NCH  81
#define C_   256
#define H_   80
#define W_   160
#define N_   8
#define HW_  (H_ * W_)
#define NROWS (N_ * H_)      // 640 work units (one per (n,y))
#define CC   4
#define P_   5
#define F2W  (W_ + 2*MAXD)   // 168
#define NQ4  (F2W / 4)       // 42
#define NTHREADS (DD * 32)   // 288
#define NCHUNK (C_ / CC)     // 64
#define NBLOCKS 296          // 148 SMs * 2 CTAs

#define S1_FLOATS (2 * CC * W_)
#define S2_FLOATS (2 * CC * DD * F2W)
#define SMEM_BYTES ((S1_FLOATS + S2_FLOATS) * 4)  // 53504 B

__device__ int g_row_ctr;

__global__ void reset_ctr_kernel() { g_row_ctr = 0; }

__device__ __forceinline__ void cp16(float* dst_smem, const float* src_gmem) {
    unsigned d = (unsigned)__cvta_generic_to_shared(dst_smem);
    asm volatile("cp.async.cg.shared.global [%0], [%1], 16;" :: "r"(d), "l"(src_gmem));
}
#define CP_COMMIT() asm volatile("cp.async.commit_group;")
#define CP_WAIT0()  asm volatile("cp.async.wait_group 0;" ::: "memory")

__global__ __launch_bounds__(NTHREADS, 2)
void corr_leaky_kernel(const float* __restrict__ f1,
                       const float* __restrict__ f2,
                       float* __restrict__ out)
{
    extern __shared__ __align__(16) float smem[];
    float* s1 = smem;               // [2][CC][W_]
    float* s2 = smem + S1_FLOATS;   // [2][CC][DD][F2W]
#define S1REF(b,c,x)   s1[((b)*CC + (c))*W_ + (x)]
#define S2REF(b,c,r,j) s2[(((b)*CC + (c))*DD + (r))*F2W + (j)]
    __shared__ int s_row;

    const int tid  = threadIdx.x;
    const int dy   = tid >> 5;
    const int lane = tid & 31;
    const int x0   = lane * P_;

    // f1 staging: one float4 per thread for tid < 160
    const int f1c  = tid / 40;
    const int f1j4 = tid - f1c * 40;
    const bool f1ok = (tid < CC * (W_ / 4));

    const float scale = 1.0f / (float)C_;

    for (;;) {
        // ---- grab next row ----
        if (tid == 0) s_row = atomicAdd(&g_row_ctr, 1);
        __syncthreads();
        const int row = s_row;
        __syncthreads();           // s_row read by all before next overwrite
        if (row >= NROWS) break;

        const int n = row / H_;
        const int y = row - n * H_;

        const int img_base = n * C_ * HW_;
        const int  gy    = y + dy - MAXD;
        const bool rowok = ((unsigned)gy < (unsigned)H_);
        const float* f1base = f1 + img_base + y * W_;
        const float* f2base = f2 + img_base + gy * W_;

        // ---- set pad slots (borders of each padded row) in BOTH buffers ----
        const float4 z4 = make_float4(0.f, 0.f, 0.f, 0.f);
#pragma unroll
        for (int b = 0; b < 2; b++)
#pragma unroll
            for (int c = 0; c < CC; c++) {
                if (rowok) {
                    if (lane == 0) *(float4*)&S2REF(b, c, dy, 0) = z4;
                    if (lane == 1) *(float4*)&S2REF(b, c, dy, 4 * (NQ4 - 1)) = z4;
                } else {
                    *(float4*)&S2REF(b, c, dy, 4 * lane) = z4;
                    if (lane < NQ4 - 32) *(float4*)&S2REF(b, c, dy, 4 * (32 + lane)) = z4;
                }
            }

        float acc[P_][DD];
#pragma unroll
        for (int p = 0; p < P_; p++)
#pragma unroll
            for (int dx = 0; dx < DD; dx++) acc[p][dx] = 0.0f;

        // ---- prologue: prefetch chunk 0 into buffer 0 ----
        if (f1ok) cp16(&S1REF(0, f1c, 4 * f1j4), f1base + f1c * HW_ + 4 * f1j4);
        if (rowok) {
#pragma unroll
            for (int c = 0; c < CC; c++) {
                const float* rowp = f2base + c * HW_;
                if (lane >= 1) cp16(&S2REF(0, c, dy, 4 * lane),        rowp + 4 * lane - 4);
                if (lane <= 8) cp16(&S2REF(0, c, dy, 4 * (32 + lane)), rowp + 4 * (32 + lane) - 4);
            }
        }
        CP_COMMIT();

        for (int i = 0; i < NCHUNK; i++) {
            const int cur = i & 1;
            CP_WAIT0();
            __syncthreads();

            if (i + 1 < NCHUNK) {
                const int nb = cur ^ 1;
                const int c0 = (i + 1) * CC;
                if (f1ok) cp16(&S1REF(nb, f1c, 4 * f1j4),
                               f1base + (c0 + f1c) * HW_ + 4 * f1j4);
                if (rowok) {
#pragma unroll
                    for (int c = 0; c < CC; c++) {
                        const float* rowp = f2base + (c0 + c) * HW_;
                        if (lane >= 1) cp16(&S2REF(nb, c, dy, 4 * lane),        rowp + 4 * lane - 4);
                        if (lane <= 8) cp16(&S2REF(nb, c, dy, 4 * (32 + lane)), rowp + 4 * (32 + lane) - 4);
                    }
                }
                CP_COMMIT();
            }

            // ---- compute on buf[cur]: per channel 18 LDS feed 45 FFMA ----
#pragma unroll
            for (int cc = 0; cc < CC; cc++) {
                float a[P_];
                float b[P_ + DD - 1];
#pragma unroll
                for (int p = 0; p < P_; p++) a[p] = S1REF(cur, cc, x0 + p);
#pragma unroll
                for (int k = 0; k < P_ + DD - 1; k++) b[k] = S2REF(cur, cc, dy, x0 + k);
#pragma unroll
                for (int p = 0; p < P_; p++)
#pragma unroll
                    for (int dx = 0; dx < DD; dx++)
                        acc[p][dx] = fmaf(a[p], b[p + dx], acc[p][dx]);
            }
        }

        // ---- epilogue: /C, LeakyReLU(0.1), store ----
        const int out_base = n * NCH * HW_ + y * W_;
#pragma unroll
        for (int dx = 0; dx < DD; dx++) {
            const int ch = dy * DD + dx;
            float* orow = out + out_base + ch * HW_;
#pragma unroll
            for (int p = 0; p < P_; p++) {
                float v = acc[p][dx] * scale;
                v = (v > 0.0f) ? v : 0.1f * v;
                orow[x0 + p] = v;
            }
        }

        __syncthreads();   // all stores/reads of this row done before rebinding smem
    }
}

extern "C" void kernel_launch(void* const* d_in, const int* in_sizes, int n_in,
                              void* d_out, int out_size)
{
    const float* feat1 = (const float*)d_in[0];
    const float* feat2 = (const float*)d_in[1];
    float* out = (float*)d_out;
    cudaFuncSetAttribute(corr_leaky_kernel,
                         cudaFuncAttributeMaxDynamicSharedMemorySize, SMEM_BYTES);
    reset_ctr_kernel<<<1, 1>>>();
    corr_leaky_kernel<<<NBLOCKS, NTHREADS, SMEM_BYTES>>>(feat1, feat2, out);
}